// round 1
// baseline (speedup 1.0000x reference)
#include <cuda_runtime.h>
#include <cstdint>

// Problem constants (fixed by setup_inputs)
#define B_      16
#define T_      1024
#define D_      384
#define MAXDUR_ 4
#define OUTLEN_ (T_ * MAXDUR_)      // 4096
#define D4_     (D_ / 4)            // 96 float4 per row

// Scratch: per-output-frame source index, -1 => pad (zero fill)
__device__ int g_idx[B_ * OUTLEN_];

// ---------------------------------------------------------------------------
// Kernel 1: per-batch inclusive scan of durations + searchsorted index table.
// 16 blocks (one per batch row), 1024 threads.
// ---------------------------------------------------------------------------
__global__ void scan_idx_kernel(const int* __restrict__ ds) {
    __shared__ int cs[T_];
    const int b   = blockIdx.x;
    const int tid = threadIdx.x;

    cs[tid] = ds[b * T_ + tid];
    __syncthreads();

    // Hillis-Steele inclusive scan over 1024 elements (10 rounds)
    #pragma unroll
    for (int off = 1; off < T_; off <<= 1) {
        int add = (tid >= off) ? cs[tid - off] : 0;
        __syncthreads();
        cs[tid] += add;
        __syncthreads();
    }

    const int total = cs[T_ - 1];

    // Each thread resolves 4 output frames: first i with cs[i] > t
    #pragma unroll
    for (int k = 0; k < OUTLEN_ / T_; k++) {
        const int t = tid + k * T_;
        int r = -1;
        if (t < total) {
            int lo = 0, hi = T_ - 1;
            #pragma unroll
            for (int s = 0; s < 10; s++) {
                int mid = (lo + hi) >> 1;
                if (cs[mid] > t) hi = mid; else lo = mid + 1;
            }
            r = lo;
        }
        g_idx[b * OUTLEN_ + t] = r;
    }
}

// ---------------------------------------------------------------------------
// Kernel 2: streaming gather. One block per output row, one float4 per thread.
// Pad rows (idx < 0) are zero-filled directly — no separate memset pass.
// ---------------------------------------------------------------------------
__global__ void __launch_bounds__(D4_) gather_kernel(
    const float4* __restrict__ xs, float4* __restrict__ out) {
    const int row = blockIdx.x;          // 0 .. B*OUTLEN-1
    const int c   = threadIdx.x;         // 0 .. 95
    const int b   = row >> 12;           // row / 4096
    const int idx = g_idx[row];          // broadcast load

    float4 v = make_float4(0.f, 0.f, 0.f, 0.f);
    if (idx >= 0) {
        v = __ldg(&xs[((size_t)(b * T_ + idx)) * D4_ + c]);
    }
    out[(size_t)row * D4_ + c] = v;
}

extern "C" void kernel_launch(void* const* d_in, const int* in_sizes, int n_in,
                              void* d_out, int out_size) {
    const float* xs = (const float*)d_in[0];   // (16,1024,384) f32
    const int*   ds = (const int*)d_in[1];     // (16,1024) i32
    float* out = (float*)d_out;                // (16,4096,384) f32

    scan_idx_kernel<<<B_, T_>>>(ds);
    gather_kernel<<<B_ * OUTLEN_, D4_>>>((const float4*)xs, (float4*)out);
}

// round 2
// speedup vs baseline: 2.1570x; 2.1570x over previous
#include <cuda_runtime.h>
#include <cstdint>

// Problem constants (fixed by setup_inputs)
#define B_      16
#define T_      1024
#define D_      384
#define MAXDUR_ 4
#define OUTLEN_ (T_ * MAXDUR_)      // 4096
#define D4_     (D_ / 4)            // 96 float4 per row

#define G_THREADS 384               // gather CTA size
#define ROWS_PER_CTA 16             // 16 rows * 96 f4 = 1536 = 384 * 4 iters

// Scratch: per-output-frame source index, -1 => pad (zero fill)
__device__ int g_idx[B_ * OUTLEN_];

// ---------------------------------------------------------------------------
// Kernel 1: warp-shuffle inclusive scan of durations + scatter-expand of the
// index table. 16 blocks (one per batch row), 1024 threads. Each token i
// writes its own index into its [start, end) output slots (<=4 writes), then
// the pad tail [total, 4096) is filled with -1 cooperatively.
// ---------------------------------------------------------------------------
__global__ void __launch_bounds__(T_) scan_idx_kernel(const int* __restrict__ ds) {
    __shared__ int wsum[32];
    const int b    = blockIdx.x;
    const int tid  = threadIdx.x;
    const int lane = tid & 31;
    const int warp = tid >> 5;

    const int d = ds[b * T_ + tid];

    // warp-level inclusive scan
    int x = d;
    #pragma unroll
    for (int off = 1; off < 32; off <<= 1) {
        int y = __shfl_up_sync(0xffffffffu, x, off);
        if (lane >= off) x += y;
    }
    if (lane == 31) wsum[warp] = x;
    __syncthreads();

    // scan the 32 warp totals with warp 0
    if (warp == 0) {
        int w = wsum[lane];
        #pragma unroll
        for (int off = 1; off < 32; off <<= 1) {
            int y = __shfl_up_sync(0xffffffffu, w, off);
            if (lane >= off) w += y;
        }
        wsum[lane] = w;
    }
    __syncthreads();

    const int base  = (warp > 0) ? wsum[warp - 1] : 0;
    const int end   = base + x;          // inclusive cumsum for token tid
    const int start = end - d;
    const int total = wsum[31];

    int* __restrict__ gi = &g_idx[b * OUTLEN_];

    // scatter-expand: token tid covers output frames [start, end)
    for (int t = start; t < end; t++) gi[t] = tid;

    // pad tail
    for (int t = total + tid; t < OUTLEN_; t += T_) gi[t] = -1;
}

// ---------------------------------------------------------------------------
// Kernel 2: streaming gather with MLP=4. One CTA handles 16 output rows.
// Batch idx loads, then batch xs loads, then streaming stores.
// ---------------------------------------------------------------------------
__global__ void __launch_bounds__(G_THREADS) gather_kernel(
    const float4* __restrict__ xs, float4* __restrict__ out) {
    const int lr   = threadIdx.x / D4_;        // 0..3 local row within slice
    const int c    = threadIdx.x - lr * D4_;   // 0..95 column
    const int row0 = blockIdx.x * ROWS_PER_CTA;
    const int b    = row0 >> 12;               // same batch for all 16 rows
    const float4* __restrict__ xb = xs + (size_t)b * T_ * D4_;

    // batch the 4 independent idx loads
    int idxs[4];
    #pragma unroll
    for (int k = 0; k < 4; k++)
        idxs[k] = g_idx[row0 + k * 4 + lr];

    // batch the 4 independent gathers
    float4 v[4];
    #pragma unroll
    for (int k = 0; k < 4; k++) {
        if (idxs[k] >= 0)
            v[k] = __ldg(&xb[(size_t)idxs[k] * D4_ + c]);
        else
            v[k] = make_float4(0.f, 0.f, 0.f, 0.f);
    }

    // streaming stores (write-once data, don't pollute L2)
    #pragma unroll
    for (int k = 0; k < 4; k++)
        __stcs(&out[(size_t)(row0 + k * 4 + lr) * D4_ + c], v[k]);
}

extern "C" void kernel_launch(void* const* d_in, const int* in_sizes, int n_in,
                              void* d_out, int out_size) {
    const float* xs = (const float*)d_in[0];   // (16,1024,384) f32
    const int*   ds = (const int*)d_in[1];     // (16,1024) i32
    float* out = (float*)d_out;                // (16,4096,384) f32

    scan_idx_kernel<<<B_, T_>>>(ds);
    gather_kernel<<<(B_ * OUTLEN_) / ROWS_PER_CTA, G_THREADS>>>(
        (const float4*)xs, (float4*)out);
}